// round 1
// baseline (speedup 1.0000x reference)
#include <cuda_runtime.h>

#define NN   50000
#define OBS  15
#define H    64
#define G4   256      // 4*H gate rows
#define TILE 64       // neighbors per block
#define WP   260      // padded row stride of transposed W_hh in smem (floats)
#define HP   68       // padded row stride of h state in smem (floats)

__device__ float g_social[16 * H];   // 4x4 grid x H pooled sums

__device__ __forceinline__ float sigf(float x) {
    // 1/(1+e^-x): MUFU.EX2 + MUFU.RCP, ~1e-7 rel error
    return __fdividef(1.0f, 1.0f + __expf(-x));
}
__device__ __forceinline__ float tanhf_(float x) {
    return 2.0f * sigf(2.0f * x) - 1.0f;
}

// ---------------------------------------------------------------------------
// Kernel 1: 15-step LSTM over all neighbors, states resident on-SM.
// Block = 64 neighbors, 256 threads. Thread (tx=lane, ty=warp) owns
// neighbors 8*ty..8*ty+7 and hidden units 2*tx, 2*tx+1 (all four gates),
// so c lives in registers and the nonlinearity is thread-local.
// ---------------------------------------------------------------------------
__global__ void __launch_bounds__(256)
neighbor_kernel(const float* __restrict__ oth,   // (OBS, NN, 2)
                const int*   __restrict__ mask,  // (OBS, NN)
                const float* __restrict__ tgt,   // (OBS, 1, 2)
                const float* __restrict__ W_ih,  // (256, 2)
                const float* __restrict__ b_ih,  // (256)
                const float* __restrict__ W_hh,  // (256, 64)
                const float* __restrict__ b_hh)  // (256)
{
    extern __shared__ float sm[];
    float* Ws   = sm;                 // [64][WP]  Ws[k][j] = W_hh[j][k]
    float* hs   = Ws + H * WP;        // [64][HP]  hs[hidden][neighbor]
    float* xs   = hs + H * HP;        // [128]     x for this step (64 n x 2)
    float* bins = xs + 128;           // [16*H]    per-block social partials

    const int tid = threadIdx.x;
    const int tx  = tid & 31;
    const int ty  = tid >> 5;
    const int n0  = blockIdx.x * TILE;

    // Load W_hh transposed (coalesced global read; 4-way smem conflict, once)
    for (int idx = tid; idx < G4 * H; idx += 256) {
        int j = idx >> 6, k = idx & 63;
        Ws[k * WP + j] = W_hh[idx];
    }
    for (int idx = tid; idx < H * HP; idx += 256) hs[idx] = 0.0f;
    for (int idx = tid; idx < 16 * H; idx += 256) bins[idx] = 0.0f;

    // Per-thread gate-row constants: j = 64*q + 2*tx + u  (q=gate, u=0/1)
    float wx0[8], wx1[8], bb[8];
    #pragma unroll
    for (int q = 0; q < 4; q++)
        #pragma unroll
        for (int u = 0; u < 2; u++) {
            int j = 64 * q + 2 * tx + u;
            wx0[q * 2 + u] = W_ih[2 * j];
            wx1[q * 2 + u] = W_ih[2 * j + 1];
            bb [q * 2 + u] = b_ih[j] + b_hh[j];
        }

    float creg[8][2];
    #pragma unroll
    for (int i = 0; i < 8; i++) { creg[i][0] = 0.0f; creg[i][1] = 0.0f; }
    float hnew[8][2];
    #pragma unroll
    for (int i = 0; i < 8; i++) { hnew[i][0] = 0.0f; hnew[i][1] = 0.0f; }

    for (int t = 0; t < OBS; t++) {
        // Stage this step's x (128 contiguous floats)
        if (tid < 128) {
            int gi = n0 * 2 + tid;
            xs[tid] = (gi < NN * 2) ? oth[(size_t)t * NN * 2 + gi] : 0.0f;
        }
        __syncthreads();   // xs ready; previous step's hs writes visible

        // acc[i][2q+u] = bias + W_ih * x
        float acc[8][8];
        #pragma unroll
        for (int i = 0; i < 8; i++) {
            float x0 = xs[2 * (8 * ty + i)];
            float x1 = xs[2 * (8 * ty + i) + 1];
            #pragma unroll
            for (int g = 0; g < 8; g++)
                acc[i][g] = bb[g] + wx0[g] * x0 + wx1[g] * x1;
        }

        // GEMM: acc += h @ W_hh^T  (h broadcast per warp, W conflict-free)
        const float* hrow = hs + 8 * ty;
        const float* wcol = Ws + 2 * tx;
        #pragma unroll 4
        for (int k = 0; k < H; k++) {
            float4 hA = *(const float4*)(hrow + k * HP);
            float4 hB = *(const float4*)(hrow + k * HP + 4);
            float2 w0 = *(const float2*)(wcol + k * WP);
            float2 w1 = *(const float2*)(wcol + k * WP + 64);
            float2 w2 = *(const float2*)(wcol + k * WP + 128);
            float2 w3 = *(const float2*)(wcol + k * WP + 192);
            float hh[8] = {hA.x, hA.y, hA.z, hA.w, hB.x, hB.y, hB.z, hB.w};
            #pragma unroll
            for (int i = 0; i < 8; i++) {
                acc[i][0] += w0.x * hh[i];  acc[i][1] += w0.y * hh[i];
                acc[i][2] += w1.x * hh[i];  acc[i][3] += w1.y * hh[i];
                acc[i][4] += w2.x * hh[i];  acc[i][5] += w2.y * hh[i];
                acc[i][6] += w3.x * hh[i];  acc[i][7] += w3.y * hh[i];
            }
        }

        // LSTM nonlinearity, thread-local
        #pragma unroll
        for (int i = 0; i < 8; i++)
            #pragma unroll
            for (int u = 0; u < 2; u++) {
                float ig = sigf (acc[i][0 + u]);
                float fg = sigf (acc[i][2 + u]);
                float gg = tanhf_(acc[i][4 + u]);
                float og = sigf (acc[i][6 + u]);
                float c  = fg * creg[i][u] + ig * gg;
                creg[i][u] = c;
                hnew[i][u] = og * tanhf_(c);
            }

        __syncthreads();   // all reads of old hs done
        #pragma unroll
        for (int u = 0; u < 2; u++) {
            float4 a = {hnew[0][u], hnew[1][u], hnew[2][u], hnew[3][u]};
            float4 b = {hnew[4][u], hnew[5][u], hnew[6][u], hnew[7][u]};
            *(float4*)(hs + (2 * tx + u) * HP + 8 * ty)     = a;
            *(float4*)(hs + (2 * tx + u) * HP + 8 * ty + 4) = b;
        }
    }
    __syncthreads();

    // Social pooling at final step only (xs still holds x at t=14)
    float ref0 = tgt[(OBS - 1) * 2];
    float ref1 = tgt[(OBS - 1) * 2 + 1];
    #pragma unroll
    for (int i = 0; i < 8; i++) {
        int nl = 8 * ty + i;
        int gn = n0 + nl;
        if (gn < NN) {
            float rx = xs[2 * nl]     - ref0;
            float ry = xs[2 * nl + 1] - ref1;
            int   m  = mask[(size_t)(OBS - 1) * NN + gn];
            // cw = ch = NS/GX = 1.0, hx = hy = 2, half = 2.0
            bool within = (fabsf(rx) <= 2.0f) && (fabsf(ry) <= 2.0f);
            int cx = (int)truncf(rx) + 2;
            int cy = (int)truncf(ry) + 2;
            bool valid = within && cx >= 0 && cx < 4 && cy >= 0 && cy < 4 && (m != 0);
            if (valid) {
                int b = cy * 4 + cx;
                atomicAdd(&bins[b * H + 2 * tx],     hnew[i][0]);
                atomicAdd(&bins[b * H + 2 * tx + 1], hnew[i][1]);
            }
        }
    }
    __syncthreads();
    for (int idx = tid; idx < 16 * H; idx += 256)
        atomicAdd(&g_social[idx], bins[idx]);
}

// ---------------------------------------------------------------------------
// Kernel 2: target LSTM (15 steps, 1 cell) + social MLP + classifier.
// ---------------------------------------------------------------------------
__global__ void __launch_bounds__(256)
head_kernel(const float* __restrict__ tgt,
            const float* __restrict__ W_ih, const float* __restrict__ b_ih,
            const float* __restrict__ W_hh, const float* __restrict__ b_hh,
            const float* __restrict__ W1,  const float* __restrict__ b1,
            const float* __restrict__ W2,  const float* __restrict__ b2,
            const float* __restrict__ Wc,  const float* __restrict__ bc,
            float* __restrict__ out)
{
    __shared__ float h[H], c[H], gates[G4], hid1[H], comb[H];
    int tid = threadIdx.x;
    if (tid < H) { h[tid] = 0.0f; c[tid] = 0.0f; }
    __syncthreads();

    for (int t = 0; t < OBS; t++) {
        float x0 = tgt[t * 2], x1 = tgt[t * 2 + 1];
        float g = b_ih[tid] + b_hh[tid] + W_ih[2 * tid] * x0 + W_ih[2 * tid + 1] * x1;
        #pragma unroll 8
        for (int k = 0; k < H; k++) g += W_hh[tid * H + k] * h[k];
        gates[tid] = g;
        __syncthreads();
        if (tid < H) {
            float ig = sigf (gates[tid]);
            float fg = sigf (gates[H   + tid]);
            float gg = tanhf_(gates[2*H + tid]);
            float og = sigf (gates[3*H + tid]);
            float cn = fg * c[tid] + ig * gg;
            c[tid] = cn;
            h[tid] = og * tanhf_(cn);
        }
        __syncthreads();
    }

    if (tid < H) {
        float a = b1[tid];
        #pragma unroll 8
        for (int p = 0; p < 16 * H; p++) a += W1[tid * 16 * H + p] * g_social[p];
        hid1[tid] = fmaxf(a, 0.0f);
    }
    __syncthreads();
    if (tid < H) {
        float a = b2[tid];
        #pragma unroll 8
        for (int k = 0; k < H; k++) a += W2[tid * H + k] * hid1[k];
        comb[tid] = h[tid] + a;
    }
    __syncthreads();
    if (tid < 2) {
        float a = bc[tid];
        #pragma unroll 8
        for (int k = 0; k < H; k++) a += Wc[tid * H + k] * comb[k];
        out[tid] = a;
    }
}

// ---------------------------------------------------------------------------
extern "C" void kernel_launch(void* const* d_in, const int* in_sizes, int n_in,
                              void* d_out, int out_size)
{
    const float* tgt  = (const float*)d_in[0];
    const float* oth  = (const float*)d_in[1];
    const int*   mask = (const int*)  d_in[2];
    const float* W_ih = (const float*)d_in[3];
    const float* b_ih = (const float*)d_in[4];
    const float* W_hh = (const float*)d_in[5];
    const float* b_hh = (const float*)d_in[6];
    const float* W1   = (const float*)d_in[7];
    const float* b1   = (const float*)d_in[8];
    const float* W2   = (const float*)d_in[9];
    const float* b2   = (const float*)d_in[10];
    const float* Wc   = (const float*)d_in[11];
    const float* bc   = (const float*)d_in[12];

    // zero the pooled-social scratch (graph-capturable, no allocation)
    void* sp = nullptr;
    cudaGetSymbolAddress(&sp, g_social);
    cudaMemsetAsync(sp, 0, 16 * H * sizeof(float));

    size_t smem = (size_t)(H * WP + H * HP + 128 + 16 * H) * sizeof(float);
    cudaFuncSetAttribute((const void*)neighbor_kernel,
                         cudaFuncAttributeMaxDynamicSharedMemorySize, (int)smem);

    int grid = (NN + TILE - 1) / TILE;   // 782 blocks
    neighbor_kernel<<<grid, 256, smem>>>(oth, mask, tgt, W_ih, b_ih, W_hh, b_hh);
    head_kernel<<<1, 256>>>(tgt, W_ih, b_ih, W_hh, b_hh,
                            W1, b1, W2, b2, Wc, bc, (float*)d_out);
}

// round 2
// speedup vs baseline: 1.2582x; 1.2582x over previous
#include <cuda_runtime.h>

#define NN   50000
#define OBS  15
#define H    64
#define TILE 64
#define WP   256     // row stride (floats) of transposed W_hh in smem
#define HP   72      // row stride (floats) of h state in smem

typedef unsigned long long u64;

__device__ float g_social[16 * H];   // 4x4 grid x H pooled sums

// ---- packed fp32x2 helpers (Blackwell FFMA2) --------------------------------
__device__ __forceinline__ u64 ffma2(u64 a, u64 b, u64 c) {
    u64 d; asm("fma.rn.f32x2 %0, %1, %2, %3;" : "=l"(d) : "l"(a), "l"(b), "l"(c));
    return d;
}
__device__ __forceinline__ u64 dup2(float x) {
    u64 d; asm("mov.b64 %0, {%1, %1};" : "=l"(d) : "f"(x)); return d;
}
__device__ __forceinline__ u64 pack2(float x, float y) {
    u64 d; asm("mov.b64 %0, {%1, %2};" : "=l"(d) : "f"(x), "f"(y)); return d;
}
__device__ __forceinline__ float2 unpack2(u64 a) {
    float2 r; asm("mov.b64 {%0, %1}, %2;" : "=f"(r.x), "=f"(r.y) : "l"(a)); return r;
}
// ---- activations ------------------------------------------------------------
__device__ __forceinline__ float tanh_ap(float x) {          // MUFU.TANH
    float y; asm("tanh.approx.f32 %0, %1;" : "=f"(y) : "f"(x)); return y;
}
__device__ __forceinline__ float sig_ap(float x) {           // 1 MUFU + 2 FMA
    return fmaf(0.5f, tanh_ap(0.5f * x), 0.5f);
}
__device__ __forceinline__ float sigf(float x) {             // accurate (head)
    return __fdividef(1.0f, 1.0f + __expf(-x));
}
__device__ __forceinline__ float tanhf_(float x) { return 2.0f * sigf(2.0f * x) - 1.0f; }

// ---------------------------------------------------------------------------
// Kernel 1: 15-step LSTM over all neighbors, FFMA2 register-blocked GEMM.
// Block = 64 neighbors, 256 threads. Thread (tx,ty) owns neighbor pairs
// (8ty+2p, 8ty+2p+1), p=0..3, and hidden units 2tx,2tx+1 of all 4 gates.
// Accumulators are f32x2 pairs over neighbors; h pairs come free from
// float4 smem loads; w is replicated via mov.b64.
// ---------------------------------------------------------------------------
__global__ void __launch_bounds__(256)
neighbor_kernel(const float* __restrict__ oth,   // (OBS, NN, 2)
                const int*   __restrict__ mask,  // (OBS, NN)
                const float* __restrict__ tgt,   // (OBS, 1, 2)
                const float* __restrict__ W_ih,  // (256, 2)
                const float* __restrict__ b_ih,  // (256)
                const float* __restrict__ W_hh,  // (256, 64)
                const float* __restrict__ b_hh)  // (256)
{
    extern __shared__ float sm[];
    u64*   cpk  = (u64*)sm;               // [3][8][32] packed per-(g,tx) consts
    float* Ws   = sm + 1536;              // [64][WP]  Ws[k][j] = W_hh[j][k]
    float* hs0  = Ws  + 64 * WP;          // [64][HP]  double-buffered h state
    float* hs1  = hs0 + 64 * HP;
    float* xs   = hs1 + 64 * HP;          // [2][128]  double-buffered x
    float* bins = xs  + 256;              // [16*H]    social partials

    const int tid = threadIdx.x;
    const int tx  = tid & 31;
    const int ty  = tid >> 5;
    const int n0  = blockIdx.x * TILE;

    // W_hh transposed into smem (coalesced global read, once)
    for (int idx = tid; idx < 256 * 64; idx += 256) {
        int j = idx >> 6, k = idx & 63;
        Ws[k * WP + j] = W_hh[idx];
    }
    // packed constants: entry (g, lx): gate row j = 64*(g>>1) + 2*lx + (g&1)
    {
        int g = tid >> 5, lx = tid & 31;
        int j = 64 * (g >> 1) + 2 * lx + (g & 1);
        cpk[      tid] = dup2(b_ih[j] + b_hh[j]);
        cpk[256 + tid] = dup2(W_ih[2 * j]);
        cpk[512 + tid] = dup2(W_ih[2 * j + 1]);
    }
    for (int i = tid; i < 64 * HP; i += 256) { hs0[i] = 0.0f; hs1[i] = 0.0f; }
    for (int i = tid; i < 16 * H;  i += 256) bins[i] = 0.0f;

    float creg[4][2][2];
    #pragma unroll
    for (int p = 0; p < 4; p++)
        #pragma unroll
        for (int u = 0; u < 2; u++) { creg[p][u][0] = 0.0f; creg[p][u][1] = 0.0f; }

    float* hcur = hs0;
    float* hnxt = hs1;

    #pragma unroll 1
    for (int t = 0; t < OBS; t++) {
        float* xst = xs + (t & 1) * 128;
        if (tid < 128) {
            int gi = n0 * 2 + tid;
            xst[tid] = (gi < NN * 2) ? oth[(size_t)t * NN * 2 + gi] : 0.0f;
        }
        __syncthreads();   // xst staged; prev-step h writes to hcur visible

        // acc[p][g] = (bias + W_ih*x) for neighbor pair p, gate-slot g=2q+u
        u64 acc[4][8];
        u64 xp0[4], xp1[4];
        #pragma unroll
        for (int p = 0; p < 4; p++) {
            int na = 8 * ty + 2 * p;
            xp0[p] = pack2(xst[2 * na],     xst[2 * na + 2]);
            xp1[p] = pack2(xst[2 * na + 1], xst[2 * na + 3]);
        }
        #pragma unroll
        for (int g = 0; g < 8; g++) {
            u64 bbp = cpk[        g * 32 + tx];
            u64 w0p = cpk[256 +   g * 32 + tx];
            u64 w1p = cpk[512 +   g * 32 + tx];
            #pragma unroll
            for (int p = 0; p < 4; p++)
                acc[p][g] = ffma2(w1p, xp1[p], ffma2(w0p, xp0[p], bbp));
        }

        // GEMM: acc += h @ W_hh^T, packed over neighbor pairs
        const float* hrow = hcur + 8 * ty;
        const float* wcol = Ws + 2 * tx;
        #pragma unroll 8
        for (int k = 0; k < H; k++) {
            float4 hA = *(const float4*)(hrow + k * HP);
            float4 hB = *(const float4*)(hrow + k * HP + 4);
            float2 w0 = *(const float2*)(wcol + k * WP);
            float2 w1 = *(const float2*)(wcol + k * WP + 64);
            float2 w2 = *(const float2*)(wcol + k * WP + 128);
            float2 w3 = *(const float2*)(wcol + k * WP + 192);
            u64 h2[4] = { pack2(hA.x, hA.y), pack2(hA.z, hA.w),
                          pack2(hB.x, hB.y), pack2(hB.z, hB.w) };
            u64 wp[8] = { dup2(w0.x), dup2(w0.y), dup2(w1.x), dup2(w1.y),
                          dup2(w2.x), dup2(w2.y), dup2(w3.x), dup2(w3.y) };
            #pragma unroll
            for (int p = 0; p < 4; p++) {
                acc[p][0] = ffma2(wp[0], h2[p], acc[p][0]);
                acc[p][1] = ffma2(wp[1], h2[p], acc[p][1]);
                acc[p][2] = ffma2(wp[2], h2[p], acc[p][2]);
                acc[p][3] = ffma2(wp[3], h2[p], acc[p][3]);
                acc[p][4] = ffma2(wp[4], h2[p], acc[p][4]);
                acc[p][5] = ffma2(wp[5], h2[p], acc[p][5]);
                acc[p][6] = ffma2(wp[6], h2[p], acc[p][6]);
                acc[p][7] = ffma2(wp[7], h2[p], acc[p][7]);
            }
        }

        // LSTM nonlinearity (tanh.approx) + write h to the other buffer
        #pragma unroll
        for (int p = 0; p < 4; p++) {
            #pragma unroll
            for (int u = 0; u < 2; u++) {
                float2 I = unpack2(acc[p][0 + u]);
                float2 F = unpack2(acc[p][2 + u]);
                float2 G = unpack2(acc[p][4 + u]);
                float2 O = unpack2(acc[p][6 + u]);
                float ca = fmaf(sig_ap(F.x), creg[p][u][0], sig_ap(I.x) * tanh_ap(G.x));
                float cb = fmaf(sig_ap(F.y), creg[p][u][1], sig_ap(I.y) * tanh_ap(G.y));
                creg[p][u][0] = ca;  creg[p][u][1] = cb;
                float2 hv = make_float2(sig_ap(O.x) * tanh_ap(ca),
                                        sig_ap(O.y) * tanh_ap(cb));
                *(float2*)(hnxt + (2 * tx + u) * HP + 8 * ty + 2 * p) = hv;
            }
        }
        float* tmp = hcur; hcur = hnxt; hnxt = tmp;
    }
    __syncthreads();

    // Social pooling at final step (hcur = final h; xs buffer 0 holds t=14's x)
    const float* xs14 = xs + ((OBS - 1) & 1) * 128;
    float ref0 = tgt[(OBS - 1) * 2];
    float ref1 = tgt[(OBS - 1) * 2 + 1];
    #pragma unroll
    for (int i = 0; i < 8; i++) {
        int nl = 8 * ty + i;
        int gn = n0 + nl;
        if (gn < NN) {
            float rx = xs14[2 * nl]     - ref0;
            float ry = xs14[2 * nl + 1] - ref1;
            int   m  = mask[(size_t)(OBS - 1) * NN + gn];
            bool within = (fabsf(rx) <= 2.0f) && (fabsf(ry) <= 2.0f);
            int cx = (int)truncf(rx) + 2;
            int cy = (int)truncf(ry) + 2;
            bool valid = within && cx >= 0 && cx < 4 && cy >= 0 && cy < 4 && (m != 0);
            if (valid) {
                int b = cy * 4 + cx;
                atomicAdd(&bins[b * H + 2 * tx],     hcur[(2 * tx)     * HP + nl]);
                atomicAdd(&bins[b * H + 2 * tx + 1], hcur[(2 * tx + 1) * HP + nl]);
            }
        }
    }
    __syncthreads();
    for (int idx = tid; idx < 16 * H; idx += 256)
        atomicAdd(&g_social[idx], bins[idx]);
}

// ---------------------------------------------------------------------------
// Kernel 2: target LSTM + social MLP + classifier. W_hh rows live in
// registers (staged via padded smem, zero per-step L1tex traffic); the
// matvecs are warp-per-row with coalesced loads + shfl reduction.
// ---------------------------------------------------------------------------
__global__ void __launch_bounds__(256)
head_kernel(const float* __restrict__ tgt,
            const float* __restrict__ W_ih, const float* __restrict__ b_ih,
            const float* __restrict__ W_hh, const float* __restrict__ b_hh,
            const float* __restrict__ W1,  const float* __restrict__ b1,
            const float* __restrict__ W2,  const float* __restrict__ b2,
            const float* __restrict__ Wc,  const float* __restrict__ bc,
            float* __restrict__ out)
{
    extern __shared__ float Wr[];                  // [256][65] padded W_hh
    __shared__ float h_s[H], c_s[H], gates[4 * H];
    __shared__ float s1[16 * H], hid[H], comb[H];
    const int tid  = threadIdx.x;
    const int lane = tid & 31;
    const int wid  = tid >> 5;

    for (int idx = tid; idx < 256 * 64; idx += 256)
        Wr[(idx >> 6) * 65 + (idx & 63)] = W_hh[idx];   // coalesced in, padded
    if (tid < H) { h_s[tid] = 0.0f; c_s[tid] = 0.0f; }
    __syncthreads();

    float w[64];
    #pragma unroll
    for (int k = 0; k < 64; k++) w[k] = Wr[tid * 65 + k];   // conflict-free LDS
    float bb  = b_ih[tid] + b_hh[tid];
    float wx0 = W_ih[2 * tid];
    float wx1 = W_ih[2 * tid + 1];

    for (int t = 0; t < OBS; t++) {
        float x0 = tgt[2 * t], x1 = tgt[2 * t + 1];
        float a0 = 0.f, a1 = 0.f, a2 = 0.f, a3 = 0.f;
        #pragma unroll
        for (int k = 0; k < 64; k += 4) {
            a0 = fmaf(w[k],     h_s[k],     a0);
            a1 = fmaf(w[k + 1], h_s[k + 1], a1);
            a2 = fmaf(w[k + 2], h_s[k + 2], a2);
            a3 = fmaf(w[k + 3], h_s[k + 3], a3);
        }
        gates[tid] = bb + wx0 * x0 + wx1 * x1 + (a0 + a1) + (a2 + a3);
        __syncthreads();
        if (tid < H) {
            float ig = sigf (gates[tid]);
            float fg = sigf (gates[H     + tid]);
            float gg = tanhf_(gates[2*H  + tid]);
            float og = sigf (gates[3*H   + tid]);
            float cn = fg * c_s[tid] + ig * gg;
            c_s[tid] = cn;
            h_s[tid] = og * tanhf_(cn);
        }
        __syncthreads();
    }

    for (int i = tid; i < 16 * H; i += 256) s1[i] = g_social[i];
    __syncthreads();

    // hid = relu(W1 @ s1 + b1): warp per 8 rows, coalesced loads, shfl reduce
    for (int r = wid * 8; r < wid * 8 + 8; r++) {
        float p = 0.f;
        #pragma unroll 8
        for (int i = 0; i < 32; i++)
            p = fmaf(W1[r * 1024 + i * 32 + lane], s1[i * 32 + lane], p);
        #pragma unroll
        for (int off = 16; off; off >>= 1) p += __shfl_xor_sync(0xffffffffu, p, off);
        if (lane == 0) hid[r] = fmaxf(p + b1[r], 0.0f);
    }
    __syncthreads();

    // comb = h + W2 @ hid + b2
    for (int r = wid * 8; r < wid * 8 + 8; r++) {
        float p = 0.f;
        #pragma unroll
        for (int i = 0; i < 2; i++)
            p = fmaf(W2[r * 64 + i * 32 + lane], hid[i * 32 + lane], p);
        #pragma unroll
        for (int off = 16; off; off >>= 1) p += __shfl_xor_sync(0xffffffffu, p, off);
        if (lane == 0) comb[r] = h_s[r] + p + b2[r];
    }
    __syncthreads();

    // out = Wc @ comb + bc (2 rows; warps 0 and 1)
    if (wid < 2) {
        float p = 0.f;
        #pragma unroll
        for (int i = 0; i < 2; i++)
            p = fmaf(Wc[wid * 64 + i * 32 + lane], comb[i * 32 + lane], p);
        #pragma unroll
        for (int off = 16; off; off >>= 1) p += __shfl_xor_sync(0xffffffffu, p, off);
        if (lane == 0) out[wid] = p + bc[wid];
    }
}

// ---------------------------------------------------------------------------
extern "C" void kernel_launch(void* const* d_in, const int* in_sizes, int n_in,
                              void* d_out, int out_size)
{
    const float* tgt  = (const float*)d_in[0];
    const float* oth  = (const float*)d_in[1];
    const int*   mask = (const int*)  d_in[2];
    const float* W_ih = (const float*)d_in[3];
    const float* b_ih = (const float*)d_in[4];
    const float* W_hh = (const float*)d_in[5];
    const float* b_hh = (const float*)d_in[6];
    const float* W1   = (const float*)d_in[7];
    const float* b1   = (const float*)d_in[8];
    const float* W2   = (const float*)d_in[9];
    const float* b2   = (const float*)d_in[10];
    const float* Wc   = (const float*)d_in[11];
    const float* bc   = (const float*)d_in[12];

    void* sp = nullptr;
    cudaGetSymbolAddress(&sp, g_social);
    cudaMemsetAsync(sp, 0, 16 * H * sizeof(float));

    // smem: cpk 1536 + Ws 16384 + hs 2*4608 + xs 256 + bins 1024 = 28416 floats
    const int smemN = 28416 * 4;
    cudaFuncSetAttribute((const void*)neighbor_kernel,
                         cudaFuncAttributeMaxDynamicSharedMemorySize, smemN);
    const int smemH = 256 * 65 * 4;
    cudaFuncSetAttribute((const void*)head_kernel,
                         cudaFuncAttributeMaxDynamicSharedMemorySize, smemH);

    int grid = (NN + TILE - 1) / TILE;   // 782 blocks
    neighbor_kernel<<<grid, 256, smemN>>>(oth, mask, tgt, W_ih, b_ih, W_hh, b_hh);
    head_kernel<<<1, 256, smemH>>>(tgt, W_ih, b_ih, W_hh, b_hh,
                                   W1, b1, W2, b2, Wc, bc, (float*)d_out);
}